// round 11
// baseline (speedup 1.0000x reference)
#include <cuda_runtime.h>
#include <cstdint>

#define B_TOT   8192
#define NF      32
#define D       64
#define NIX     496
#define BT      256       // batch rows per CTA
#define NTHREADS 128      // 4 warps, each owns M=64 rows, full N=64
#define STRIDE  68        // sP/sK row stride (floats): main-loop conflict-free
#define QSTRIDE 72        // sQ row stride (floats): epilogue conflict-free
#define NGRP    136       // sum over r of ceil((31-r)/4)
#define PAIRS_PER_CTA 4

#define SP_F (BT * STRIDE)     // 17408
#define SK_F (64 * STRIDE)     // 4352
#define SQ_F (64 * QSTRIDE)    // 4608  (64-row strip chunk)
#define SMEM_FLOATS (SP_F + SK_F + SQ_F)   // 26368 floats = 105472 B -> 2 CTA/SM

__device__ __forceinline__ float f2tf32(float f) {
    uint32_t r; asm("cvt.rn.tf32.f32 %0, %1;" : "=r"(r) : "f"(f));
    return __uint_as_float(r);
}
__device__ __forceinline__ void mma_tf32(float d[4], const uint32_t a[4], const uint32_t b[2]) {
    asm volatile(
        "mma.sync.aligned.m16n8k8.row.col.f32.tf32.tf32.f32 "
        "{%0,%1,%2,%3}, {%4,%5,%6,%7}, {%8,%9}, {%0,%1,%2,%3};"
        : "+f"(d[0]), "+f"(d[1]), "+f"(d[2]), "+f"(d[3])
        : "r"(a[0]), "r"(a[1]), "r"(a[2]), "r"(a[3]), "r"(b[0]), "r"(b[1]));
}

extern "C" __global__ void __launch_bounds__(NTHREADS, 2)
opn_mma10_kernel(const float* __restrict__ x,
                 const float* __restrict__ kern,
                 float* __restrict__ out)
{
    const int gx   = blockIdx.x;      // pair-group 0..135
    const int bblk = blockIdx.y;
    const int tid  = threadIdx.x;
    const int wid  = tid >> 5;
    const int lane = tid & 31;
    const int b0   = bblk * BT;

    // decode group -> (r, j): groups per r = ceil((31-r)/4) = (34-r)>>2
    int r = 0, g2 = gx;
    while (g2 >= ((34 - r) >> 2)) { g2 -= (34 - r) >> 2; r++; }
    const int cbase = r + 1 + 4 * g2;
    const int nbase = r * 31 - (r * (r - 1)) / 2;

    extern __shared__ float smem[];
    float* sP = smem;
    float* sK = sP + SP_F;
    float* sQ = sK + SK_F;

    const int f4 = tid & 15;     // 16B chunk within a 64-float row
    const int rb = tid >> 4;     // 0..7

    // ---------------- P tile (tf32) loaded ONCE for the group ----------------
    {
        const float4* xp4 = (const float4*)(x + ((size_t)b0 * NF + r) * D);
        #pragma unroll
        for (int pass = 0; pass < 32; ++pass) {
            int b = rb + pass * 8;
            float4 v = __ldg(xp4 + (size_t)b * (NF * D / 4) + f4);
            float4 t = { f2tf32(v.x), f2tf32(v.y), f2tf32(v.z), f2tf32(v.w) };
            *(float4*)&sP[b * STRIDE + f4 * 4] = t;
        }
    }

    const int g    = lane >> 2;   // 0..7
    const int tig  = lane & 3;    // 0..3
    const int rowW = wid * 64;

    for (int t = 0; t < PAIRS_PER_CTA; ++t) {
        const int c = cbase + t;
        if (c > 31) break;                 // uniform across CTA
        const int n = nbase + (c - r - 1);

        // ---- load K_n (tf32) into sK ----
        // (prev pair's sK reads finished before its mt=0 stage-sync; safe to overwrite)
        #pragma unroll
        for (int pass = 0; pass < 8; ++pass) {
            int o = rb + pass * 8;
            const float4* kp4 = (const float4*)(kern + ((size_t)o * NIX + n) * D);
            float4 v = __ldg(kp4 + f4);
            float4 tt = { f2tf32(v.x), f2tf32(v.y), f2tf32(v.z), f2tf32(v.w) };
            *(float4*)&sK[o * STRIDE + f4 * 4] = tt;
        }
        __syncthreads();

        // ---- MMA main loop: warp owns M=64 rows (mt=0..3), full N=64, K=64 ----
        float acc[4][8][4];
        #pragma unroll
        for (int mt = 0; mt < 4; ++mt)
            #pragma unroll
            for (int q = 0; q < 8; ++q)
                #pragma unroll
                for (int j = 0; j < 4; ++j) acc[mt][q][j] = 0.0f;

        #pragma unroll
        for (int ks = 0; ks < 8; ++ks) {
            const int k0 = ks * 8;
            uint32_t a[4][4];
            #pragma unroll
            for (int mt = 0; mt < 4; ++mt) {
                const int rowA = rowW + mt * 16;
                a[mt][0] = __float_as_uint(sP[(rowA + g)     * STRIDE + k0 + tig]);
                a[mt][1] = __float_as_uint(sP[(rowA + g + 8) * STRIDE + k0 + tig]);
                a[mt][2] = __float_as_uint(sP[(rowA + g)     * STRIDE + k0 + tig + 4]);
                a[mt][3] = __float_as_uint(sP[(rowA + g + 8) * STRIDE + k0 + tig + 4]);
            }
            #pragma unroll
            for (int nt = 0; nt < 8; ++nt) {
                uint32_t b[2];
                b[0] = __float_as_uint(sK[(nt * 8 + g) * STRIDE + k0 + tig]);
                b[1] = __float_as_uint(sK[(nt * 8 + g) * STRIDE + k0 + tig + 4]);
                #pragma unroll
                for (int mt = 0; mt < 4; ++mt)
                    mma_tf32(acc[mt][nt], a[mt], b);
            }
        }

        // ---- epilogue in 4 chunks: stage 64 Q rows (one 16-row strip per warp) ----
        // chunk mt covers global rows { w*64 + mt*16 + (0..15) : w=0..3 },
        // stored at sQ local row l = w*16 + (row&15).
        #pragma unroll
        for (int mt = 0; mt < 4; ++mt) {
            __syncthreads();               // prior chunk's sQ reads done (mt=0: after MMA)
            #pragma unroll
            for (int pass = 0; pass < 4; ++pass) {
                int l  = rb + pass * 8;    // 0..31? no: rb 0..7, pass 0..3 -> 0..31
                // two half-steps to cover 64 rows with 128 threads * 4 passes * ... :
                // l covers 0..31 here; second half below
                int gr = (l >> 4) * 64 + mt * 16 + (l & 15);
                const float4* xq4 = (const float4*)(x + ((size_t)(b0 + gr) * NF + c) * D);
                *(float4*)&sQ[l * QSTRIDE + f4 * 4] = __ldg(xq4 + f4);
                int l2  = l + 32;
                int gr2 = (l2 >> 4) * 64 + mt * 16 + (l2 & 15);
                const float4* xq4b = (const float4*)(x + ((size_t)(b0 + gr2) * NF + c) * D);
                *(float4*)&sQ[l2 * QSTRIDE + f4 * 4] = __ldg(xq4b + f4);
            }
            __syncthreads();

            // epilogue for this mt: warp reads its own strip at local base wid*16
            const int lbase = wid * 16 + g;
            float s0 = 0.0f, s1 = 0.0f;
            #pragma unroll
            for (int nt = 0; nt < 8; ++nt) {
                const int col = nt * 8 + tig * 2;
                float2 q0 = *(const float2*)&sQ[lbase       * QSTRIDE + col];
                float2 q1 = *(const float2*)&sQ[(lbase + 8) * QSTRIDE + col];
                s0 = fmaf(acc[mt][nt][0], q0.x, fmaf(acc[mt][nt][1], q0.y, s0));
                s1 = fmaf(acc[mt][nt][2], q1.x, fmaf(acc[mt][nt][3], q1.y, s1));
            }
            s0 += __shfl_xor_sync(0xFFFFFFFFu, s0, 1, 4);
            s0 += __shfl_xor_sync(0xFFFFFFFFu, s0, 2, 4);
            s1 += __shfl_xor_sync(0xFFFFFFFFu, s1, 1, 4);
            s1 += __shfl_xor_sync(0xFFFFFFFFu, s1, 2, 4);
            if (tig == 0) {
                const int row0 = rowW + mt * 16 + g;
                out[(size_t)(b0 + row0)     * NIX + n] = s0;
                out[(size_t)(b0 + row0 + 8) * NIX + n] = s1;
            }
        }
    }
}

extern "C" void kernel_launch(void* const* d_in, const int* in_sizes, int n_in,
                              void* d_out, int out_size)
{
    (void)in_sizes; (void)n_in; (void)out_size;
    const float* x    = (const float*)d_in[0];   // (8192, 32, 64) f32
    const float* kern = (const float*)d_in[1];   // (64, 496, 64) f32
    float* out        = (float*)d_out;           // (8192, 496) f32

    const int smem_bytes = SMEM_FLOATS * (int)sizeof(float);   // 105472
    cudaFuncSetAttribute(opn_mma10_kernel, cudaFuncAttributeMaxDynamicSharedMemorySize, smem_bytes);

    dim3 grid(NGRP, B_TOT / BT);   // (136, 32)
    opn_mma10_kernel<<<grid, NTHREADS, smem_bytes>>>(x, kern, out);
}

// round 12
// speedup vs baseline: 1.0886x; 1.0886x over previous
#include <cuda_runtime.h>
#include <cstdint>

#define B_TOT   8192
#define NF      32
#define D       64
#define NIX     496
#define BT      256       // batch rows per CTA
#define NTHREADS 128      // 4 warps, each owns M=64 rows, full N=64
#define STRIDE  68        // sP/sK row stride (floats): conflict-free
#define NGRP    136       // sum over r of ceil((31-r)/4)
#define PAIRS_PER_CTA 4

#define SP_F (BT * STRIDE)     // 17408
#define SK_F (64 * STRIDE)     // 4352 (one K buffer; double-buffered)
#define SMEM_FLOATS (SP_F + 2 * SK_F)   // 26112 floats = 104448 B -> 2 CTA/SM

__device__ __forceinline__ uint32_t smem_u32(const void* p) {
    uint32_t a;
    asm("{ .reg .u64 t; cvta.to.shared.u64 t, %1; cvt.u32.u64 %0, t; }" : "=r"(a) : "l"(p));
    return a;
}
__device__ __forceinline__ float f2tf32(float f) {
    uint32_t r; asm("cvt.rn.tf32.f32 %0, %1;" : "=r"(r) : "f"(f));
    return __uint_as_float(r);
}
__device__ __forceinline__ void cp16(void* dst, const float* src) {
    uint32_t d = smem_u32(dst);
    asm volatile("cp.async.cg.shared.global [%0], [%1], 16;\n" :: "r"(d), "l"(src));
}
__device__ __forceinline__ void mma_tf32(float d[4], const uint32_t a[4], const uint32_t b[2]) {
    asm volatile(
        "mma.sync.aligned.m16n8k8.row.col.f32.tf32.tf32.f32 "
        "{%0,%1,%2,%3}, {%4,%5,%6,%7}, {%8,%9}, {%0,%1,%2,%3};"
        : "+f"(d[0]), "+f"(d[1]), "+f"(d[2]), "+f"(d[3])
        : "r"(a[0]), "r"(a[1]), "r"(a[2]), "r"(a[3]), "r"(b[0]), "r"(b[1]));
}

extern "C" __global__ void __launch_bounds__(NTHREADS, 2)
opn_mma11_kernel(const float* __restrict__ x,
                 const float* __restrict__ kern,
                 float* __restrict__ out)
{
    const int gx   = blockIdx.x;      // pair-group 0..135
    const int bblk = blockIdx.y;
    const int tid  = threadIdx.x;
    const int wid  = tid >> 5;
    const int lane = tid & 31;
    const int b0   = bblk * BT;

    // decode group -> (r, j): groups per r = ceil((31-r)/4) = (34-r)>>2
    int r = 0, g2 = gx;
    while (g2 >= ((34 - r) >> 2)) { g2 -= (34 - r) >> 2; r++; }
    const int cbase = r + 1 + 4 * g2;
    const int nbase = r * 31 - (r * (r - 1)) / 2;

    extern __shared__ float smem[];
    float* sP  = smem;
    float* sK0 = sP + SP_F;           // double buffer: sK0 + (t&1)*SK_F

    const int f4 = tid & 15;     // 16B chunk within a 64-float row
    const int rb = tid >> 4;     // 0..7

    // ---- prefetch K for pair 0 (raw f32; HW tf32-truncates in MMA) ----
    {
        const int n0 = nbase + (cbase - r - 1);
        #pragma unroll
        for (int pass = 0; pass < 8; ++pass) {
            int o = rb + pass * 8;
            cp16(&sK0[o * STRIDE + f4 * 4],
                 kern + ((size_t)o * NIX + n0) * D + f4 * 4);
        }
        asm volatile("cp.async.commit_group;\n" ::: "memory");
    }

    // ---------------- P tile (RN tf32) loaded ONCE for the group ----------------
    {
        const float4* xp4 = (const float4*)(x + ((size_t)b0 * NF + r) * D);
        #pragma unroll
        for (int pass = 0; pass < 32; ++pass) {
            int b = rb + pass * 8;
            float4 v = __ldg(xp4 + (size_t)b * (NF * D / 4) + f4);
            float4 t = { f2tf32(v.x), f2tf32(v.y), f2tf32(v.z), f2tf32(v.w) };
            *(float4*)&sP[b * STRIDE + f4 * 4] = t;
        }
    }

    const int g    = lane >> 2;   // 0..7
    const int tig  = lane & 3;    // 0..3
    const int rowW = wid * 64;

    for (int t = 0; t < PAIRS_PER_CTA; ++t) {
        const int c = cbase + t;
        if (c > 31) break;                 // uniform across CTA
        const int n = nbase + (c - r - 1);
        const float* sK = sK0 + (t & 1) * SK_F;

        // single barrier per pair: K[t] arrived (this thread) -> visible to all
        asm volatile("cp.async.wait_group 0;\n" ::: "memory");
        __syncthreads();

        // prefetch K for pair t+1 into the other buffer (overlaps MMA+epilogue)
        if (t + 1 < PAIRS_PER_CTA && c + 1 <= 31) {
            const int n1 = n + 1;          // consecutive c -> consecutive n
            float* sKn = sK0 + ((t + 1) & 1) * SK_F;
            #pragma unroll
            for (int pass = 0; pass < 8; ++pass) {
                int o = rb + pass * 8;
                cp16(&sKn[o * STRIDE + f4 * 4],
                     kern + ((size_t)o * NIX + n1) * D + f4 * 4);
            }
            asm volatile("cp.async.commit_group;\n" ::: "memory");
        }

        // ---- MMA main loop: warp owns M=64 rows (mt=0..3), full N=64, K=64 ----
        float acc[4][8][4];
        #pragma unroll
        for (int mt = 0; mt < 4; ++mt)
            #pragma unroll
            for (int q = 0; q < 8; ++q)
                #pragma unroll
                for (int j = 0; j < 4; ++j) acc[mt][q][j] = 0.0f;

        #pragma unroll
        for (int ks = 0; ks < 8; ++ks) {
            const int k0 = ks * 8;
            uint32_t a[4][4];
            #pragma unroll
            for (int mt = 0; mt < 4; ++mt) {
                const int rowA = rowW + mt * 16;
                a[mt][0] = __float_as_uint(sP[(rowA + g)     * STRIDE + k0 + tig]);
                a[mt][1] = __float_as_uint(sP[(rowA + g + 8) * STRIDE + k0 + tig]);
                a[mt][2] = __float_as_uint(sP[(rowA + g)     * STRIDE + k0 + tig + 4]);
                a[mt][3] = __float_as_uint(sP[(rowA + g + 8) * STRIDE + k0 + tig + 4]);
            }
            #pragma unroll
            for (int nt = 0; nt < 8; ++nt) {
                uint32_t b[2];
                b[0] = __float_as_uint(sK[(nt * 8 + g) * STRIDE + k0 + tig]);
                b[1] = __float_as_uint(sK[(nt * 8 + g) * STRIDE + k0 + tig + 4]);
                #pragma unroll
                for (int mt = 0; mt < 4; ++mt)
                    mma_tf32(acc[mt][nt], a[mt], b);
            }
        }

        // ---- epilogue: out[b, n] = sum_o t[b][o] * x[b, c, o] (q from gmem) ----
        #pragma unroll
        for (int mt = 0; mt < 4; ++mt) {
            const int row0 = rowW + mt * 16 + g;
            const float* q0p = x + ((size_t)(b0 + row0)     * NF + c) * D;
            const float* q1p = x + ((size_t)(b0 + row0 + 8) * NF + c) * D;
            float s0 = 0.0f, s1 = 0.0f;
            #pragma unroll
            for (int nt = 0; nt < 8; ++nt) {
                const int col = nt * 8 + tig * 2;
                float2 q0 = __ldg((const float2*)(q0p + col));
                float2 q1 = __ldg((const float2*)(q1p + col));
                s0 = fmaf(acc[mt][nt][0], q0.x, fmaf(acc[mt][nt][1], q0.y, s0));
                s1 = fmaf(acc[mt][nt][2], q1.x, fmaf(acc[mt][nt][3], q1.y, s1));
            }
            s0 += __shfl_xor_sync(0xFFFFFFFFu, s0, 1, 4);
            s0 += __shfl_xor_sync(0xFFFFFFFFu, s0, 2, 4);
            s1 += __shfl_xor_sync(0xFFFFFFFFu, s1, 1, 4);
            s1 += __shfl_xor_sync(0xFFFFFFFFu, s1, 2, 4);
            if (tig == 0) {
                out[(size_t)(b0 + row0)     * NIX + n] = s0;
                out[(size_t)(b0 + row0 + 8) * NIX + n] = s1;
            }
        }
    }
}

extern "C" void kernel_launch(void* const* d_in, const int* in_sizes, int n_in,
                              void* d_out, int out_size)
{
    (void)in_sizes; (void)n_in; (void)out_size;
    const float* x    = (const float*)d_in[0];   // (8192, 32, 64) f32
    const float* kern = (const float*)d_in[1];   // (64, 496, 64) f32
    float* out        = (float*)d_out;           // (8192, 496) f32

    const int smem_bytes = SMEM_FLOATS * (int)sizeof(float);   // 104448
    cudaFuncSetAttribute(opn_mma11_kernel, cudaFuncAttributeMaxDynamicSharedMemorySize, smem_bytes);

    dim3 grid(NGRP, B_TOT / BT);   // (136, 32)
    opn_mma11_kernel<<<grid, NTHREADS, smem_bytes>>>(x, kern, out);
}